// round 1
// baseline (speedup 1.0000x reference)
#include <cuda_runtime.h>
#include <math.h>

#define D_MODEL 1024
#define SEQ     2048
#define BATCH   2
#define ROWS    (BATCH*SEQ)   // 4096 tokens
#define NHEADS  16
#define HDIM    64
#define DFF     4096
#define EPS     1e-9f

// ---------------- scratch (static device globals; no runtime allocation) ----
__device__ float g_xn [ROWS*D_MODEL];  // LN output (reused ln1/ln2)
__device__ float g_q  [ROWS*D_MODEL];
__device__ float g_k  [ROWS*D_MODEL];
__device__ float g_v  [ROWS*D_MODEL];
__device__ float g_att[ROWS*D_MODEL];  // attention pre-out, [row, h*64+d]
__device__ float g_h1 [ROWS*D_MODEL];  // x + attn_proj
__device__ float g_mid[ROWS*DFF];      // gelu(x @ W_up^T)

// ---------------- LayerNorm (unbiased variance, ddof=1) ---------------------
__global__ __launch_bounds__(256)
void ln_kernel(const float* __restrict__ x, const float* __restrict__ ms,
               const float* __restrict__ ss, float* __restrict__ y)
{
    int row = blockIdx.x;
    int tid = threadIdx.x;
    const float4 v = *(const float4*)&x[row*D_MODEL + tid*4];
    float s  = v.x + v.y + v.z + v.w;
    float sq = v.x*v.x + v.y*v.y + v.z*v.z + v.w*v.w;

    // warp reduce
    #pragma unroll
    for (int off = 16; off; off >>= 1) {
        s  += __shfl_xor_sync(0xffffffffu, s,  off);
        sq += __shfl_xor_sync(0xffffffffu, sq, off);
    }
    __shared__ float rs[8], rq[8];
    if ((tid & 31) == 0) { rs[tid>>5] = s; rq[tid>>5] = sq; }
    __syncthreads();
    float ts = 0.f, tq = 0.f;
    #pragma unroll
    for (int i = 0; i < 8; i++) { ts += rs[i]; tq += rq[i]; }

    float mean = ts * (1.0f/D_MODEL);
    float var  = (tq - (float)D_MODEL * mean * mean) * (1.0f/(D_MODEL-1));
    float rstd = rsqrtf(var + EPS);

    const float4 sv = *(const float4*)&ss[tid*4];
    const float4 mv = *(const float4*)&ms[tid*4];
    float4 o;
    o.x = (v.x - mean) * rstd * sv.x + mv.x;
    o.y = (v.y - mean) * rstd * sv.y + mv.y;
    o.z = (v.z - mean) * rstd * sv.z + mv.z;
    o.w = (v.w - mean) * rstd * sv.w + mv.w;
    *(float4*)&y[row*D_MODEL + tid*4] = o;
}

// ---------------- GEMM: C[M,N] = A[M,K] @ W[N,K]^T (+ epilogue) -------------
// EPI: 0 = none, 1 = exact GELU, 2 = add residual R (same layout as C)
#define BM 64
#define BN 64
#define BK 16

template<int EPI>
__global__ __launch_bounds__(256)
void gemm_kernel(const float* __restrict__ A, const float* __restrict__ W,
                 float* __restrict__ C, const float* __restrict__ R,
                 int M, int N, int K)
{
    __shared__ float As[BK][BM];
    __shared__ float Ws[BK][BN];

    int tid = threadIdx.x;
    int tx = tid & 15;        // 0..15 -> output col quad
    int ty = tid >> 4;        // 0..15 -> output row quad
    int rowBase = blockIdx.y * BM;
    int colBase = blockIdx.x * BN;

    int lr = tid >> 2;        // 0..63 (tile row for loading)
    int lk = (tid & 3) * 4;   // k offset 0,4,8,12

    const float* Ag = &A[(size_t)(rowBase + lr) * K + lk];
    const float* Wg = &W[(size_t)(colBase + lr) * K + lk];

    float acc[4][4];
    #pragma unroll
    for (int i = 0; i < 4; i++)
        #pragma unroll
        for (int j = 0; j < 4; j++) acc[i][j] = 0.f;

    for (int k0 = 0; k0 < K; k0 += BK) {
        float4 a4 = *(const float4*)(Ag + k0);
        float4 w4 = *(const float4*)(Wg + k0);
        As[lk+0][lr] = a4.x; As[lk+1][lr] = a4.y;
        As[lk+2][lr] = a4.z; As[lk+3][lr] = a4.w;
        Ws[lk+0][lr] = w4.x; Ws[lk+1][lr] = w4.y;
        Ws[lk+2][lr] = w4.z; Ws[lk+3][lr] = w4.w;
        __syncthreads();

        #pragma unroll
        for (int k = 0; k < BK; k++) {
            float4 av = *(const float4*)&As[k][ty*4];
            float4 wv = *(const float4*)&Ws[k][tx*4];
            float a[4] = {av.x, av.y, av.z, av.w};
            float w[4] = {wv.x, wv.y, wv.z, wv.w};
            #pragma unroll
            for (int i = 0; i < 4; i++)
                #pragma unroll
                for (int j = 0; j < 4; j++)
                    acc[i][j] = fmaf(a[i], w[j], acc[i][j]);
        }
        __syncthreads();
    }

    #pragma unroll
    for (int i = 0; i < 4; i++) {
        int row = rowBase + ty*4 + i;
        size_t off = (size_t)row * N + colBase + tx*4;
        float4 o;
        o.x = acc[i][0]; o.y = acc[i][1]; o.z = acc[i][2]; o.w = acc[i][3];
        if (EPI == 1) {
            o.x = 0.5f*o.x*(1.f + erff(o.x*0.70710678118654752f));
            o.y = 0.5f*o.y*(1.f + erff(o.y*0.70710678118654752f));
            o.z = 0.5f*o.z*(1.f + erff(o.z*0.70710678118654752f));
            o.w = 0.5f*o.w*(1.f + erff(o.w*0.70710678118654752f));
        } else if (EPI == 2) {
            float4 r4 = *(const float4*)&R[off];
            o.x += r4.x; o.y += r4.y; o.z += r4.z; o.w += r4.w;
        }
        *(float4*)&C[off] = o;
    }
}

// ---------------- causal attention (flash-style, fp32) ----------------------
// grid: (SEQ/64, NHEADS, BATCH), block: 256 threads.
// Thread t owns query row r = t/4 of the tile and 16 score-cols / 16 out-dims
// (quad q = t&3, offset q*16). Online softmax across key tiles jt <= qt.
#define TP 65   // padded row stride in smem (bank-conflict mitigation)
#define ATTN_SMEM (4 * 64 * TP * (int)sizeof(float))

__global__ __launch_bounds__(256)
void attn_kernel(const float* __restrict__ Qf, const float* __restrict__ Kf,
                 const float* __restrict__ Vf, float* __restrict__ Of)
{
    extern __shared__ float sm[];
    float* Qs = sm;              // [64][TP]
    float* Ks = Qs + 64*TP;
    float* Vs = Ks + 64*TP;
    float* Ps = Vs + 64*TP;

    int qt = blockIdx.x, h = blockIdx.y, b = blockIdx.z;
    int tid = threadIdx.x;
    int r  = tid >> 2;           // 0..63 query row within tile
    int c0 = (tid & 3) * 16;     // quad's 16-col / 16-dim window

    int qrow0 = b*SEQ + qt*64;
    // load Q tile (64 rows x 64 dims of this head)
    #pragma unroll
    for (int it = 0; it < 4; it++) {
        int e  = tid + it*256;        // float4 index, 1024 total
        int rr = e >> 4;
        int cc = (e & 15) * 4;
        float4 v = *(const float4*)&Qf[(size_t)(qrow0 + rr)*D_MODEL + h*HDIM + cc];
        Qs[rr*TP + cc+0] = v.x; Qs[rr*TP + cc+1] = v.y;
        Qs[rr*TP + cc+2] = v.z; Qs[rr*TP + cc+3] = v.w;
    }

    float m = -INFINITY, l = 0.f;
    float acc[16];
    #pragma unroll
    for (int d = 0; d < 16; d++) acc[d] = 0.f;

    for (int jt = 0; jt <= qt; jt++) {
        __syncthreads();  // prior tile fully consumed before overwrite
        int krow0 = b*SEQ + jt*64;
        #pragma unroll
        for (int it = 0; it < 4; it++) {
            int e  = tid + it*256;
            int rr = e >> 4;
            int cc = (e & 15) * 4;
            size_t goff = (size_t)(krow0 + rr)*D_MODEL + h*HDIM + cc;
            float4 kv = *(const float4*)&Kf[goff];
            float4 vv = *(const float4*)&Vf[goff];
            Ks[rr*TP + cc+0] = kv.x; Ks[rr*TP + cc+1] = kv.y;
            Ks[rr*TP + cc+2] = kv.z; Ks[rr*TP + cc+3] = kv.w;
            Vs[rr*TP + cc+0] = vv.x; Vs[rr*TP + cc+1] = vv.y;
            Vs[rr*TP + cc+2] = vv.z; Vs[rr*TP + cc+3] = vv.w;
        }
        __syncthreads();

        // scores for 16 columns
        float sv[16];
        bool last = (jt == qt);
        #pragma unroll 4
        for (int cc = 0; cc < 16; cc++) {
            int c = c0 + cc;
            float s = 0.f;
            #pragma unroll
            for (int k = 0; k < HDIM; k++)
                s = fmaf(Qs[r*TP + k], Ks[c*TP + k], s);
            s *= 0.125f;  // 1/sqrt(64)
            if (last && c > r) s = -INFINITY;   // causal mask (only diag tile)
            sv[cc] = s;
        }

        // row max across quad
        float tm = sv[0];
        #pragma unroll
        for (int cc = 1; cc < 16; cc++) tm = fmaxf(tm, sv[cc]);
        tm = fmaxf(tm, __shfl_xor_sync(0xffffffffu, tm, 1));
        tm = fmaxf(tm, __shfl_xor_sync(0xffffffffu, tm, 2));

        float mnew  = fmaxf(m, tm);
        float alpha = __expf(m - mnew);

        float lsum = 0.f;
        #pragma unroll
        for (int cc = 0; cc < 16; cc++) {
            float p = __expf(sv[cc] - mnew);
            Ps[r*TP + c0 + cc] = p;
            lsum += p;
        }
        lsum += __shfl_xor_sync(0xffffffffu, lsum, 1);
        lsum += __shfl_xor_sync(0xffffffffu, lsum, 2);

        l = l * alpha + lsum;
        m = mnew;
        #pragma unroll
        for (int d = 0; d < 16; d++) acc[d] *= alpha;

        __syncwarp();  // P row produced by this quad (same warp) before use

        #pragma unroll 8
        for (int c = 0; c < 64; c++) {
            float pv = Ps[r*TP + c];
            #pragma unroll
            for (int d = 0; d < 16; d++)
                acc[d] = fmaf(pv, Vs[c*TP + c0 + d], acc[d]);
        }
    }

    float inv = 1.0f / l;
    size_t obase = (size_t)(qrow0 + r)*D_MODEL + h*HDIM + c0;
    #pragma unroll
    for (int d4 = 0; d4 < 4; d4++) {
        float4 o;
        o.x = acc[d4*4+0]*inv; o.y = acc[d4*4+1]*inv;
        o.z = acc[d4*4+2]*inv; o.w = acc[d4*4+3]*inv;
        *(float4*)&Of[obase + d4*4] = o;
    }
}

// ---------------- launcher --------------------------------------------------
extern "C" void kernel_launch(void* const* d_in, const int* in_sizes, int n_in,
                              void* d_out, int out_size)
{
    const float* x      = (const float*)d_in[0];
    const float* Wq     = (const float*)d_in[1];
    const float* Wk     = (const float*)d_in[2];
    const float* Wv     = (const float*)d_in[3];
    const float* Wo     = (const float*)d_in[4];
    const float* Wup    = (const float*)d_in[5];
    const float* Wdown  = (const float*)d_in[6];
    const float* ln1m   = (const float*)d_in[7];
    const float* ln1s   = (const float*)d_in[8];
    const float* ln2m   = (const float*)d_in[9];
    const float* ln2s   = (const float*)d_in[10];
    float* out = (float*)d_out;

    float *xn, *q, *k, *v, *att, *h1, *mid;
    cudaGetSymbolAddress((void**)&xn,  g_xn);
    cudaGetSymbolAddress((void**)&q,   g_q);
    cudaGetSymbolAddress((void**)&k,   g_k);
    cudaGetSymbolAddress((void**)&v,   g_v);
    cudaGetSymbolAddress((void**)&att, g_att);
    cudaGetSymbolAddress((void**)&h1,  g_h1);
    cudaGetSymbolAddress((void**)&mid, g_mid);

    cudaFuncSetAttribute(attn_kernel,
                         cudaFuncAttributeMaxDynamicSharedMemorySize, ATTN_SMEM);

    dim3 gsq(D_MODEL/BN, ROWS/BM);   // (16, 64) for N=1024
    dim3 gup(DFF/BN,     ROWS/BM);   // (64, 64) for N=4096

    // 1. LN1
    ln_kernel<<<ROWS, 256>>>(x, ln1m, ln1s, xn);
    // 2-4. Q, K, V projections
    gemm_kernel<0><<<gsq, 256>>>(xn, Wq, q, nullptr, ROWS, D_MODEL, D_MODEL);
    gemm_kernel<0><<<gsq, 256>>>(xn, Wk, k, nullptr, ROWS, D_MODEL, D_MODEL);
    gemm_kernel<0><<<gsq, 256>>>(xn, Wv, v, nullptr, ROWS, D_MODEL, D_MODEL);
    // 5. causal attention
    attn_kernel<<<dim3(SEQ/64, NHEADS, BATCH), 256, ATTN_SMEM>>>(q, k, v, att);
    // 6. O projection + residual -> h1
    gemm_kernel<2><<<gsq, 256>>>(att, Wo, h1, x, ROWS, D_MODEL, D_MODEL);
    // 7. LN2
    ln_kernel<<<ROWS, 256>>>(h1, ln2m, ln2s, xn);
    // 8. up-proj + exact GELU
    gemm_kernel<1><<<gup, 256>>>(xn, Wup, mid, nullptr, ROWS, DFF, D_MODEL);
    // 9. down-proj + residual -> output
    gemm_kernel<2><<<gsq, 256>>>(mid, Wdown, out, h1, ROWS, D_MODEL, DFF);
}

// round 4
// speedup vs baseline: 4.2700x; 4.2700x over previous
#include <cuda_runtime.h>
#include <cuda_bf16.h>
#include <math.h>
#include <stdint.h>

#define D_MODEL 1024
#define SEQ     2048
#define BATCH   2
#define ROWS    (BATCH*SEQ)   // 4096 tokens
#define NHEADS  16
#define HDIM    64
#define DFF     4096
#define EPS     1e-9f

typedef unsigned short ushort_t;

// ---------------- scratch (static device globals) ---------------------------
__device__ float    g_h1[ROWS*D_MODEL];
__device__ ushort_t g_xh[ROWS*D_MODEL], g_xl[ROWS*D_MODEL];   // LN out hi/lo
__device__ ushort_t g_qh[ROWS*D_MODEL], g_ql[ROWS*D_MODEL];
__device__ ushort_t g_kh[ROWS*D_MODEL], g_kl[ROWS*D_MODEL];
__device__ ushort_t g_vh[ROWS*D_MODEL], g_vl[ROWS*D_MODEL];
__device__ ushort_t g_ah[ROWS*D_MODEL], g_al[ROWS*D_MODEL];   // attn out hi/lo
__device__ ushort_t g_mh[ROWS*DFF],     g_ml[ROWS*DFF];       // gelu mid hi/lo

__device__ ushort_t g_wqh[D_MODEL*D_MODEL], g_wql[D_MODEL*D_MODEL];
__device__ ushort_t g_wkh[D_MODEL*D_MODEL], g_wkl[D_MODEL*D_MODEL];
__device__ ushort_t g_wvh[D_MODEL*D_MODEL], g_wvl[D_MODEL*D_MODEL];
__device__ ushort_t g_woh[D_MODEL*D_MODEL], g_wol[D_MODEL*D_MODEL];
__device__ ushort_t g_uph[DFF*D_MODEL],     g_upl[DFF*D_MODEL];
__device__ ushort_t g_dnh[D_MODEL*DFF],     g_dnl[D_MODEL*DFF];

// ---------------- helpers ----------------------------------------------------
__device__ __forceinline__ uint32_t smem_u32(const void* p) {
    uint32_t a;
    asm("{ .reg .u64 t; cvta.to.shared.u64 t, %1; cvt.u32.u64 %0, t; }" : "=r"(a) : "l"(p));
    return a;
}

__device__ __forceinline__ void ldsm4(uint32_t &r0, uint32_t &r1, uint32_t &r2,
                                      uint32_t &r3, uint32_t a) {
    asm volatile("ldmatrix.sync.aligned.m8n8.x4.shared.b16 {%0,%1,%2,%3}, [%4];"
        : "=r"(r0), "=r"(r1), "=r"(r2), "=r"(r3) : "r"(a));
}
__device__ __forceinline__ void ldsm4t(uint32_t &r0, uint32_t &r1, uint32_t &r2,
                                       uint32_t &r3, uint32_t a) {
    asm volatile("ldmatrix.sync.aligned.m8n8.x4.trans.shared.b16 {%0,%1,%2,%3}, [%4];"
        : "=r"(r0), "=r"(r1), "=r"(r2), "=r"(r3) : "r"(a));
}
__device__ __forceinline__ void mma_bf16(float &c0, float &c1, float &c2, float &c3,
        uint32_t a0, uint32_t a1, uint32_t a2, uint32_t a3, uint32_t b0, uint32_t b1) {
    asm volatile("mma.sync.aligned.m16n8k16.row.col.f32.bf16.bf16.f32 "
        "{%0,%1,%2,%3}, {%4,%5,%6,%7}, {%8,%9}, {%0,%1,%2,%3};"
        : "+f"(c0), "+f"(c1), "+f"(c2), "+f"(c3)
        : "r"(a0), "r"(a1), "r"(a2), "r"(a3), "r"(b0), "r"(b1));
}

__device__ __forceinline__ void split1(float x, ushort_t& h, ushort_t& l) {
    __nv_bfloat16 hb = __float2bfloat16(x);
    float hf = __bfloat162float(hb);
    __nv_bfloat16 lb = __float2bfloat16(x - hf);
    h = __bfloat16_as_ushort(hb);
    l = __bfloat16_as_ushort(lb);
}
__device__ __forceinline__ void split2(float x, float y, uint32_t &h, uint32_t &l) {
    __nv_bfloat16 hx = __float2bfloat16(x);
    __nv_bfloat16 hy = __float2bfloat16(y);
    __nv_bfloat16 lx = __float2bfloat16(x - __bfloat162float(hx));
    __nv_bfloat16 ly = __float2bfloat16(y - __bfloat162float(hy));
    __nv_bfloat162 hp = __halves2bfloat162(hx, hy);
    __nv_bfloat162 lp = __halves2bfloat162(lx, ly);
    h = *reinterpret_cast<uint32_t*>(&hp);
    l = *reinterpret_cast<uint32_t*>(&lp);
}

// ---------------- fp32 -> bf16 hi/lo conversion ------------------------------
__global__ __launch_bounds__(256)
void conv_kernel(const float* __restrict__ s, ushort_t* __restrict__ hi,
                 ushort_t* __restrict__ lo, int n)
{
    int i = (blockIdx.x * 256 + threadIdx.x) * 4;
    if (i >= n) return;
    float4 v = *(const float4*)&s[i];
    ushort_t h[4], l[4];
    split1(v.x, h[0], l[0]); split1(v.y, h[1], l[1]);
    split1(v.z, h[2], l[2]); split1(v.w, h[3], l[3]);
    *(uint2*)&hi[i] = *(uint2*)h;
    *(uint2*)&lo[i] = *(uint2*)l;
}

// ---------------- LayerNorm (writes bf16 hi/lo) ------------------------------
__global__ __launch_bounds__(256)
void ln_kernel(const float* __restrict__ x, const float* __restrict__ ms,
               const float* __restrict__ ss, ushort_t* __restrict__ yh,
               ushort_t* __restrict__ yl)
{
    int row = blockIdx.x;
    int tid = threadIdx.x;
    const float4 v = *(const float4*)&x[row*D_MODEL + tid*4];
    float s  = v.x + v.y + v.z + v.w;
    float sq = v.x*v.x + v.y*v.y + v.z*v.z + v.w*v.w;
    #pragma unroll
    for (int off = 16; off; off >>= 1) {
        s  += __shfl_xor_sync(0xffffffffu, s,  off);
        sq += __shfl_xor_sync(0xffffffffu, sq, off);
    }
    __shared__ float rs[8], rq[8];
    if ((tid & 31) == 0) { rs[tid>>5] = s; rq[tid>>5] = sq; }
    __syncthreads();
    float ts = 0.f, tq = 0.f;
    #pragma unroll
    for (int i = 0; i < 8; i++) { ts += rs[i]; tq += rq[i]; }
    float mean = ts * (1.0f/D_MODEL);
    float var  = (tq - (float)D_MODEL * mean * mean) * (1.0f/(D_MODEL-1));
    float rstd = rsqrtf(var + EPS);
    const float4 sv = *(const float4*)&ss[tid*4];
    const float4 mv = *(const float4*)&ms[tid*4];
    float o[4];
    o[0] = (v.x - mean)*rstd*sv.x + mv.x;
    o[1] = (v.y - mean)*rstd*sv.y + mv.y;
    o[2] = (v.z - mean)*rstd*sv.z + mv.z;
    o[3] = (v.w - mean)*rstd*sv.w + mv.w;
    ushort_t h[4], l[4];
    #pragma unroll
    for (int i = 0; i < 4; i++) split1(o[i], h[i], l[i]);
    *(uint2*)&yh[row*D_MODEL + tid*4] = *(uint2*)h;
    *(uint2*)&yl[row*D_MODEL + tid*4] = *(uint2*)l;
}

// ---------------- mma.sync split-bf16 GEMM -----------------------------------
// C[M,N] = (Ah+Al)[M,K] @ (Wh+Wl)[N,K]^T
// EPI: 0 -> write Ch/Cl hi/lo ; 1 -> gelu then Ch/Cl ; 2 -> Cf = acc + R (fp32)
#define ROWB  80                       // 32 bf16 = 64B + 16B pad (conflict-free)
#define ARRB  (128*ROWB)               // 10240 per array
#define STAGE (4*ARRB)                 // 40960
#define GEMM_SMEM (2*STAGE)

template<int EPI>
__global__ __launch_bounds__(256, 1)
void gemm_mma(const ushort_t* __restrict__ Ah, const ushort_t* __restrict__ Al,
              const ushort_t* __restrict__ Wh, const ushort_t* __restrict__ Wl,
              float* __restrict__ Cf, ushort_t* __restrict__ Ch,
              ushort_t* __restrict__ Cl, const float* __restrict__ R,
              int N, int K)
{
    extern __shared__ char smem[];
    uint32_t sb = smem_u32(smem);
    uint32_t st[2] = { sb, sb + STAGE };

    int tid  = threadIdx.x;
    int lane = tid & 31;
    int wid  = tid >> 5;
    int wm   = wid & 3;        // 4 warps over M (32 rows each)
    int wn   = wid >> 2;       // 2 warps over N (64 cols each)
    int rowBase = blockIdx.y * 128;
    int colBase = blockIdx.x * 128;
    int NS = K >> 5;           // K/32 slabs

    float acc[2][8][4];
    #pragma unroll
    for (int a = 0; a < 2; a++)
        #pragma unroll
        for (int b = 0; b < 8; b++)
            #pragma unroll
            for (int c = 0; c < 4; c++) acc[a][b][c] = 0.f;

    auto load_slab = [&](uint32_t stg, int k0) {
        #pragma unroll
        for (int t = 0; t < 8; t++) {
            int c   = tid + t*256;        // 2048 16B-chunks
            int arr = c >> 9;             // 0 Ah,1 Al,2 Wh,3 Wl
            int e   = c & 511;
            int row = e >> 2;
            int c16 = (e & 3) << 4;
            const ushort_t* src = (arr == 0) ? Ah : (arr == 1) ? Al
                                 : (arr == 2) ? Wh : Wl;
            int gr = ((arr < 2) ? rowBase : colBase) + row;
            src += (size_t)gr * K + k0 + (c16 >> 1);
            uint32_t dst = stg + arr*ARRB + row*ROWB + c16;
            asm volatile("cp.async.cg.shared.global [%0], [%1], 16;" :: "r"(dst), "l"(src));
        }
        asm volatile("cp.async.commit_group;" ::: "memory");
    };

    load_slab(st[0], 0);
    load_slab(st[1], 32);

    for (int i = 0; i < NS; i++) {
        if (i + 1 < NS) asm volatile("cp.async.wait_group 1;" ::: "memory");
        else            asm volatile("cp.async.wait_group 0;" ::: "memory");
        __syncthreads();
        uint32_t stg = st[i & 1];

        #pragma unroll
        for (int ks = 0; ks < 2; ks++) {
            uint32_t ah[2][4], al[2][4];
            #pragma unroll
            for (int mi = 0; mi < 2; mi++) {
                uint32_t ra = stg + (wm*32 + mi*16 + (lane & 15))*ROWB
                            + ks*32 + (lane & 16);
                ldsm4(ah[mi][0], ah[mi][1], ah[mi][2], ah[mi][3], ra);
                ldsm4(al[mi][0], al[mi][1], al[mi][2], al[mi][3], ra + ARRB);
            }
            #pragma unroll
            for (int pr = 0; pr < 4; pr++) {
                uint32_t bh[4], bl[4];
                uint32_t rb = stg + 2*ARRB
                            + (wn*64 + pr*16 + (lane & 7) + ((lane & 16) >> 1))*ROWB
                            + ks*32 + ((lane & 8) << 1);
                ldsm4(bh[0], bh[1], bh[2], bh[3], rb);
                ldsm4(bl[0], bl[1], bl[2], bl[3], rb + ARRB);
                #pragma unroll
                for (int mi = 0; mi < 2; mi++) {
                    float* c0 = acc[mi][2*pr];
                    float* c1 = acc[mi][2*pr+1];
                    mma_bf16(c0[0],c0[1],c0[2],c0[3], ah[mi][0],ah[mi][1],ah[mi][2],ah[mi][3], bh[0],bh[1]);
                    mma_bf16(c0[0],c0[1],c0[2],c0[3], al[mi][0],al[mi][1],al[mi][2],al[mi][3], bh[0],bh[1]);
                    mma_bf16(c0[0],c0[1],c0[2],c0[3], ah[mi][0],ah[mi][1],ah[mi][2],ah[mi][3], bl[0],bl[1]);
                    mma_bf16(c1[0],c1[1],c1[2],c1[3], ah[mi][0],ah[mi][1],ah[mi][2],ah[mi][3], bh[2],bh[3]);
                    mma_bf16(c1[0],c1[1],c1[2],c1[3], al[mi][0],al[mi][1],al[mi][2],al[mi][3], bh[2],bh[3]);
                    mma_bf16(c1[0],c1[1],c1[2],c1[3], ah[mi][0],ah[mi][1],ah[mi][2],ah[mi][3], bl[2],bl[3]);
                }
            }
        }
        __syncthreads();
        if (i + 2 < NS) load_slab(stg, (i + 2)*32);
    }

    // epilogue
    int r0 = rowBase + wm*32 + (lane >> 2);
    int c0 = colBase + wn*64 + (lane & 3)*2;
    #pragma unroll
    for (int mi = 0; mi < 2; mi++) {
        #pragma unroll
        for (int n = 0; n < 8; n++) {
            float* c = acc[mi][n];
            int r  = r0 + mi*16;
            int cc = c0 + n*8;
            size_t o1 = (size_t)r * N + cc;
            size_t o2 = (size_t)(r + 8) * N + cc;
            if (EPI == 2) {
                float2 r1 = *(const float2*)&R[o1];
                float2 r2 = *(const float2*)&R[o2];
                *(float2*)&Cf[o1] = make_float2(c[0] + r1.x, c[1] + r1.y);
                *(float2*)&Cf[o2] = make_float2(c[2] + r2.x, c[3] + r2.y);
            } else {
                float v0 = c[0], v1 = c[1], v2 = c[2], v3 = c[3];
                if (EPI == 1) {
                    v0 = 0.5f*v0*(1.f + erff(v0*0.70710678118654752f));
                    v1 = 0.5f*v1*(1.f + erff(v1*0.70710678118654752f));
                    v2 = 0.5f*v2*(1.f + erff(v2*0.70710678118654752f));
                    v3 = 0.5f*v3*(1.f + erff(v3*0.70710678118654752f));
                }
                uint32_t h, l;
                split2(v0, v1, h, l);
                *(uint32_t*)&Ch[o1] = h; *(uint32_t*)&Cl[o1] = l;
                split2(v2, v3, h, l);
                *(uint32_t*)&Ch[o2] = h; *(uint32_t*)&Cl[o2] = l;
            }
        }
    }
}

// ---------------- flash attention with mma.sync (split bf16) -----------------
// CTA: 128 threads (4 warps), one (b, h, 64-query tile). Warp w: rows w*16..+15.
#define KROWB 144                       // 64 bf16 = 128B + 16B pad
#define KARR  (64*KROWB)                // 9216 per array
// layout: Qh 0, Ql 1, Kh 2, Kl 3, Vh 4, Vl 5  (x KARR)
#define ATTN_SMEM (6*KARR)

__global__ __launch_bounds__(128, 1)
void attn_mma(const ushort_t* __restrict__ Qh_, const ushort_t* __restrict__ Ql_,
              const ushort_t* __restrict__ Kh_, const ushort_t* __restrict__ Kl_,
              const ushort_t* __restrict__ Vh_, const ushort_t* __restrict__ Vl_,
              ushort_t* __restrict__ Oh, ushort_t* __restrict__ Ol)
{
    extern __shared__ char smem[];
    uint32_t sb = smem_u32(smem);
    int qt = blockIdx.x, h = blockIdx.y, b = blockIdx.z;
    int tid  = threadIdx.x;
    int lane = tid & 31;
    int w    = tid >> 5;
    int qrow0 = b*SEQ + qt*64;

    // stage Q tile (hi/lo)
    #pragma unroll
    for (int t = 0; t < 8; t++) {
        int c   = tid + t*128;           // 1024 chunks
        int arr = c >> 9;
        int e   = c & 511;
        int row = e >> 3;
        int c16 = (e & 7) << 4;
        const ushort_t* src = (arr ? Ql_ : Qh_)
            + (size_t)(qrow0 + row)*D_MODEL + h*HDIM + (c16 >> 1);
        uint4 v = *(const uint4*)src;
        *(uint4*)(smem + arr*KARR + row*KROWB + c16) = v;
    }
    __syncthreads();

    // Q fragments (held for whole kernel)
    uint32_t qh[4][4], ql[4][4];
    #pragma unroll
    for (int ks = 0; ks < 4; ks++) {
        uint32_t ra = sb + (w*16 + (lane & 15))*KROWB + ks*32 + (lane & 16);
        ldsm4(qh[ks][0], qh[ks][1], qh[ks][2], qh[ks][3], ra);
        ldsm4(ql[ks][0], ql[ks][1], ql[ks][2], ql[ks][3], ra + KARR);
    }

    float o[8][4];
    #pragma unroll
    for (int n = 0; n < 8; n++)
        #pragma unroll
        for (int j = 0; j < 4; j++) o[n][j] = 0.f;
    float m0 = -INFINITY, m1 = -INFINITY, l0 = 0.f, l1 = 0.f;

    for (int jt = 0; jt <= qt; jt++) {
        int krow0 = b*SEQ + jt*64;
        // load K,V tiles (hi/lo)
        #pragma unroll
        for (int t = 0; t < 16; t++) {
            int c   = tid + t*128;       // 2048 chunks
            int arr = c >> 9;            // 0 Kh,1 Kl,2 Vh,3 Vl
            int e   = c & 511;
            int row = e >> 3;
            int c16 = (e & 7) << 4;
            const ushort_t* src = (arr == 0) ? Kh_ : (arr == 1) ? Kl_
                                 : (arr == 2) ? Vh_ : Vl_;
            src += (size_t)(krow0 + row)*D_MODEL + h*HDIM + (c16 >> 1);
            uint4 v = *(const uint4*)src;
            *(uint4*)(smem + (2 + arr)*KARR + row*KROWB + c16) = v;
        }
        __syncthreads();

        // S = Q K^T  (n = keys)
        float s[8][4];
        #pragma unroll
        for (int n = 0; n < 8; n++)
            #pragma unroll
            for (int j = 0; j < 4; j++) s[n][j] = 0.f;

        #pragma unroll
        for (int ks = 0; ks < 4; ks++) {
            #pragma unroll
            for (int pr = 0; pr < 4; pr++) {
                uint32_t bh[4], bl[4];
                uint32_t rb = sb + 2*KARR
                            + (pr*16 + (lane & 7) + ((lane & 16) >> 1))*KROWB
                            + ks*32 + ((lane & 8) << 1);
                ldsm4(bh[0], bh[1], bh[2], bh[3], rb);
                ldsm4(bl[0], bl[1], bl[2], bl[3], rb + KARR);
                float* s0 = s[2*pr];
                float* s1 = s[2*pr+1];
                mma_bf16(s0[0],s0[1],s0[2],s0[3], qh[ks][0],qh[ks][1],qh[ks][2],qh[ks][3], bh[0],bh[1]);
                mma_bf16(s0[0],s0[1],s0[2],s0[3], ql[ks][0],ql[ks][1],ql[ks][2],ql[ks][3], bh[0],bh[1]);
                mma_bf16(s0[0],s0[1],s0[2],s0[3], qh[ks][0],qh[ks][1],qh[ks][2],qh[ks][3], bl[0],bl[1]);
                mma_bf16(s1[0],s1[1],s1[2],s1[3], qh[ks][0],qh[ks][1],qh[ks][2],qh[ks][3], bh[2],bh[3]);
                mma_bf16(s1[0],s1[1],s1[2],s1[3], ql[ks][0],ql[ks][1],ql[ks][2],ql[ks][3], bh[2],bh[3]);
                mma_bf16(s1[0],s1[1],s1[2],s1[3], qh[ks][0],qh[ks][1],qh[ks][2],qh[ks][3], bl[2],bl[3]);
            }
        }

        // scale + causal mask (diagonal tile only)
        bool diag = (jt == qt);
        int rlo = w*16 + (lane >> 2);
        int rhi = rlo + 8;
        #pragma unroll
        for (int n = 0; n < 8; n++) {
            int cA = n*8 + (lane & 3)*2;
            int cB = cA + 1;
            s[n][0] *= 0.125f; s[n][1] *= 0.125f;
            s[n][2] *= 0.125f; s[n][3] *= 0.125f;
            if (diag) {
                if (cA > rlo) s[n][0] = -INFINITY;
                if (cB > rlo) s[n][1] = -INFINITY;
                if (cA > rhi) s[n][2] = -INFINITY;
                if (cB > rhi) s[n][3] = -INFINITY;
            }
        }

        // row max across fragments + quad lanes
        float mx0 = s[0][0], mx1 = s[0][2];
        #pragma unroll
        for (int n = 0; n < 8; n++) {
            mx0 = fmaxf(mx0, fmaxf(s[n][0], s[n][1]));
            mx1 = fmaxf(mx1, fmaxf(s[n][2], s[n][3]));
        }
        mx0 = fmaxf(mx0, __shfl_xor_sync(0xffffffffu, mx0, 1));
        mx0 = fmaxf(mx0, __shfl_xor_sync(0xffffffffu, mx0, 2));
        mx1 = fmaxf(mx1, __shfl_xor_sync(0xffffffffu, mx1, 1));
        mx1 = fmaxf(mx1, __shfl_xor_sync(0xffffffffu, mx1, 2));

        float mn0 = fmaxf(m0, mx0), mn1 = fmaxf(m1, mx1);
        float al0 = __expf(m0 - mn0), al1 = __expf(m1 - mn1);

        float ls0 = 0.f, ls1 = 0.f;
        #pragma unroll
        for (int n = 0; n < 8; n++) {
            s[n][0] = __expf(s[n][0] - mn0);
            s[n][1] = __expf(s[n][1] - mn0);
            s[n][2] = __expf(s[n][2] - mn1);
            s[n][3] = __expf(s[n][3] - mn1);
            ls0 += s[n][0] + s[n][1];
            ls1 += s[n][2] + s[n][3];
        }
        ls0 += __shfl_xor_sync(0xffffffffu, ls0, 1);
        ls0 += __shfl_xor_sync(0xffffffffu, ls0, 2);
        ls1 += __shfl_xor_sync(0xffffffffu, ls1, 1);
        ls1 += __shfl_xor_sync(0xffffffffu, ls1, 2);

        l0 = l0*al0 + ls0;  l1 = l1*al1 + ls1;
        m0 = mn0;           m1 = mn1;
        #pragma unroll
        for (int n = 0; n < 8; n++) {
            o[n][0] *= al0; o[n][1] *= al0;
            o[n][2] *= al1; o[n][3] *= al1;
        }

        // PV: o += P[16x64] * V[64x64]  (k = keys, n = dims)
        #pragma unroll
        for (int kp = 0; kp < 4; kp++) {
            uint32_t ph[4], pl[4];
            split2(s[2*kp][0],   s[2*kp][1],   ph[0], pl[0]);
            split2(s[2*kp][2],   s[2*kp][3],   ph[1], pl[1]);
            split2(s[2*kp+1][0], s[2*kp+1][1], ph[2], pl[2]);
            split2(s[2*kp+1][2], s[2*kp+1][3], ph[3], pl[3]);
            #pragma unroll
            for (int pr = 0; pr < 4; pr++) {
                uint32_t vh4[4], vl4[4];
                uint32_t rv = sb + 4*KARR
                            + (kp*16 + (lane & 7) + ((lane & 8) ? 8 : 0))*KROWB
                            + pr*32 + (lane & 16);
                ldsm4t(vh4[0], vh4[1], vh4[2], vh4[3], rv);
                ldsm4t(vl4[0], vl4[1], vl4[2], vl4[3], rv + KARR);
                float* o0 = o[2*pr];
                float* o1 = o[2*pr+1];
                mma_bf16(o0[0],o0[1],o0[2],o0[3], ph[0],ph[1],ph[2],ph[3], vh4[0],vh4[1]);
                mma_bf16(o0[0],o0[1],o0[2],o0[3], pl[0],pl[1],pl[2],pl[3], vh4[0],vh4[1]);
                mma_bf16(o0[0],o0[1],o0[2],o0[3], ph[0],ph[1],ph[2],ph[3], vl4[0],vl4[1]);
                mma_bf16(o1[0],o1[1],o1[2],o1[3], ph[0],ph[1],ph[2],ph[3], vh4[2],vh4[3]);
                mma_bf16(o1[0],o1[1],o1[2],o1[3], pl[0],pl[1],pl[2],pl[3], vh4[2],vh4[3]);
                mma_bf16(o1[0],o1[1],o1[2],o1[3], ph[0],ph[1],ph[2],ph[3], vl4[2],vl4[3]);
            }
        }
        __syncthreads();   // done reading K/V before next tile overwrites
    }

    // epilogue: normalize, split to bf16 hi/lo
    float i0 = 1.f/l0, i1 = 1.f/l1;
    int r  = qrow0 + w*16 + (lane >> 2);
    int cc = h*64 + (lane & 3)*2;
    #pragma unroll
    for (int n = 0; n < 8; n++) {
        size_t o1 = (size_t)r * D_MODEL + cc + n*8;
        size_t o2 = (size_t)(r + 8) * D_MODEL + cc + n*8;
        uint32_t hh, ll;
        split2(o[n][0]*i0, o[n][1]*i0, hh, ll);
        *(uint32_t*)&Oh[o1] = hh; *(uint32_t*)&Ol[o1] = ll;
        split2(o[n][2]*i1, o[n][3]*i1, hh, ll);
        *(uint32_t*)&Oh[o2] = hh; *(uint32_t*)&Ol[o2] = ll;
    }
}

// ---------------- launcher ---------------------------------------------------
extern "C" void kernel_launch(void* const* d_in, const int* in_sizes, int n_in,
                              void* d_out, int out_size)
{
    const float* x     = (const float*)d_in[0];
    const float* Wq    = (const float*)d_in[1];
    const float* Wk    = (const float*)d_in[2];
    const float* Wv    = (const float*)d_in[3];
    const float* Wo    = (const float*)d_in[4];
    const float* Wup   = (const float*)d_in[5];
    const float* Wdown = (const float*)d_in[6];
    const float* ln1m  = (const float*)d_in[7];
    const float* ln1s  = (const float*)d_in[8];
    const float* ln2m  = (const float*)d_in[9];
    const float* ln2s  = (const float*)d_in[10];
    float* out = (float*)d_out;

    float* h1;
    ushort_t *xh, *xl, *qh, *ql, *kh, *kl, *vh, *vl, *ah, *al, *mh, *ml;
    ushort_t *wqh, *wql, *wkh, *wkl, *wvh, *wvl, *woh, *wol, *uph, *upl, *dnh, *dnl;
    cudaGetSymbolAddress((void**)&h1, g_h1);
    cudaGetSymbolAddress((void**)&xh, g_xh); cudaGetSymbolAddress((void**)&xl, g_xl);
    cudaGetSymbolAddress((void**)&qh, g_qh); cudaGetSymbolAddress((void**)&ql, g_ql);
    cudaGetSymbolAddress((void**)&kh, g_kh); cudaGetSymbolAddress((void**)&kl, g_kl);
    cudaGetSymbolAddress((void**)&vh, g_vh); cudaGetSymbolAddress((void**)&vl, g_vl);
    cudaGetSymbolAddress((void**)&ah, g_ah); cudaGetSymbolAddress((void**)&al, g_al);
    cudaGetSymbolAddress((void**)&mh, g_mh); cudaGetSymbolAddress((void**)&ml, g_ml);
    cudaGetSymbolAddress((void**)&wqh, g_wqh); cudaGetSymbolAddress((void**)&wql, g_wql);
    cudaGetSymbolAddress((void**)&wkh, g_wkh); cudaGetSymbolAddress((void**)&wkl, g_wkl);
    cudaGetSymbolAddress((void**)&wvh, g_wvh); cudaGetSymbolAddress((void**)&wvl, g_wvl);
    cudaGetSymbolAddress((void**)&woh, g_woh); cudaGetSymbolAddress((void**)&wol, g_wol);
    cudaGetSymbolAddress((void**)&uph, g_uph); cudaGetSymbolAddress((void**)&upl, g_upl);
    cudaGetSymbolAddress((void**)&dnh, g_dnh); cudaGetSymbolAddress((void**)&dnl, g_dnl);

    cudaFuncSetAttribute(gemm_mma<0>, cudaFuncAttributeMaxDynamicSharedMemorySize, GEMM_SMEM);
    cudaFuncSetAttribute(gemm_mma<1>, cudaFuncAttributeMaxDynamicSharedMemorySize, GEMM_SMEM);
    cudaFuncSetAttribute(gemm_mma<2>, cudaFuncAttributeMaxDynamicSharedMemorySize, GEMM_SMEM);
    cudaFuncSetAttribute(attn_mma,    cudaFuncAttributeMaxDynamicSharedMemorySize, ATTN_SMEM);

    const int DD = D_MODEL * D_MODEL;
    const int DU = DFF * D_MODEL;
    conv_kernel<<<DD/1024, 256>>>(Wq,    wqh, wql, DD);
    conv_kernel<<<DD/1024, 256>>>(Wk,    wkh, wkl, DD);
    conv_kernel<<<DD/1024, 256>>>(Wv,    wvh, wvl, DD);
    conv_kernel<<<DD/1024, 256>>>(Wo,    woh, wol, DD);
    conv_kernel<<<DU/1024, 256>>>(Wup,   uph, upl, DU);
    conv_kernel<<<DU/1024, 256>>>(Wdown, dnh, dnl, DU);

    dim3 gsq(D_MODEL/128, ROWS/128);   // (8, 32)
    dim3 gup(DFF/128,     ROWS/128);   // (32, 32)

    // LN1
    ln_kernel<<<ROWS, 256>>>(x, ln1m, ln1s, xh, xl);
    // Q, K, V projections (bf16 hi/lo out)
    gemm_mma<0><<<gsq, 256, GEMM_SMEM>>>(xh, xl, wqh, wql, nullptr, qh, ql, nullptr, D_MODEL, D_MODEL);
    gemm_mma<0><<<gsq, 256, GEMM_SMEM>>>(xh, xl, wkh, wkl, nullptr, kh, kl, nullptr, D_MODEL, D_MODEL);
    gemm_mma<0><<<gsq, 256, GEMM_SMEM>>>(xh, xl, wvh, wvl, nullptr, vh, vl, nullptr, D_MODEL, D_MODEL);
    // attention
    attn_mma<<<dim3(SEQ/64, NHEADS, BATCH), 128, ATTN_SMEM>>>(qh, ql, kh, kl, vh, vl, ah, al);
    // O projection + residual
    gemm_mma<2><<<gsq, 256, GEMM_SMEM>>>(ah, al, woh, wol, h1, nullptr, nullptr, x, D_MODEL, D_MODEL);
    // LN2
    ln_kernel<<<ROWS, 256>>>(h1, ln2m, ln2s, xh, xl);
    // up-proj + GELU
    gemm_mma<1><<<gup, 256, GEMM_SMEM>>>(xh, xl, uph, upl, nullptr, mh, ml, nullptr, DFF, D_MODEL);
    // down-proj + residual -> output
    gemm_mma<2><<<gsq, 256, GEMM_SMEM>>>(mh, ml, dnh, dnl, out, nullptr, nullptr, h1, D_MODEL, DFF);
}

// round 5
// speedup vs baseline: 4.7559x; 1.1138x over previous
#include <cuda_runtime.h>
#include <cuda_bf16.h>
#include <math.h>
#include <stdint.h>

#define D_MODEL 1024
#define SEQ     2048
#define BATCH   2
#define ROWS    (BATCH*SEQ)   // 4096 tokens
#define NHEADS  16
#define HDIM    64
#define DFF     4096
#define EPS     1e-9f

typedef unsigned short ushort_t;

// ---------------- scratch (static device globals) ---------------------------
__device__ float    g_h1[ROWS*D_MODEL];
__device__ ushort_t g_xh[ROWS*D_MODEL], g_xl[ROWS*D_MODEL];   // LN out hi/lo
__device__ ushort_t g_qh[ROWS*D_MODEL], g_ql[ROWS*D_MODEL];
__device__ ushort_t g_kh[ROWS*D_MODEL], g_kl[ROWS*D_MODEL];
__device__ ushort_t g_vh[ROWS*D_MODEL], g_vl[ROWS*D_MODEL];
__device__ ushort_t g_ah[ROWS*D_MODEL], g_al[ROWS*D_MODEL];   // attn out hi/lo
__device__ ushort_t g_mh[ROWS*DFF],     g_ml[ROWS*DFF];       // gelu mid hi/lo

__device__ ushort_t g_wqh[D_MODEL*D_MODEL], g_wql[D_MODEL*D_MODEL];
__device__ ushort_t g_wkh[D_MODEL*D_MODEL], g_wkl[D_MODEL*D_MODEL];
__device__ ushort_t g_wvh[D_MODEL*D_MODEL], g_wvl[D_MODEL*D_MODEL];
__device__ ushort_t g_woh[D_MODEL*D_MODEL], g_wol[D_MODEL*D_MODEL];
__device__ ushort_t g_uph[DFF*D_MODEL],     g_upl[DFF*D_MODEL];
__device__ ushort_t g_dnh[D_MODEL*DFF],     g_dnl[D_MODEL*DFF];

// ---------------- helpers ----------------------------------------------------
__device__ __forceinline__ uint32_t smem_u32(const void* p) {
    uint32_t a;
    asm("{ .reg .u64 t; cvta.to.shared.u64 t, %1; cvt.u32.u64 %0, t; }" : "=r"(a) : "l"(p));
    return a;
}

__device__ __forceinline__ void ldsm4(uint32_t &r0, uint32_t &r1, uint32_t &r2,
                                      uint32_t &r3, uint32_t a) {
    asm volatile("ldmatrix.sync.aligned.m8n8.x4.shared.b16 {%0,%1,%2,%3}, [%4];"
        : "=r"(r0), "=r"(r1), "=r"(r2), "=r"(r3) : "r"(a));
}
__device__ __forceinline__ void ldsm4t(uint32_t &r0, uint32_t &r1, uint32_t &r2,
                                       uint32_t &r3, uint32_t a) {
    asm volatile("ldmatrix.sync.aligned.m8n8.x4.trans.shared.b16 {%0,%1,%2,%3}, [%4];"
        : "=r"(r0), "=r"(r1), "=r"(r2), "=r"(r3) : "r"(a));
}
__device__ __forceinline__ void mma_bf16(float &c0, float &c1, float &c2, float &c3,
        uint32_t a0, uint32_t a1, uint32_t a2, uint32_t a3, uint32_t b0, uint32_t b1) {
    asm volatile("mma.sync.aligned.m16n8k16.row.col.f32.bf16.bf16.f32 "
        "{%0,%1,%2,%3}, {%4,%5,%6,%7}, {%8,%9}, {%0,%1,%2,%3};"
        : "+f"(c0), "+f"(c1), "+f"(c2), "+f"(c3)
        : "r"(a0), "r"(a1), "r"(a2), "r"(a3), "r"(b0), "r"(b1));
}

__device__ __forceinline__ void split1(float x, ushort_t& h, ushort_t& l) {
    __nv_bfloat16 hb = __float2bfloat16(x);
    float hf = __bfloat162float(hb);
    __nv_bfloat16 lb = __float2bfloat16(x - hf);
    h = __bfloat16_as_ushort(hb);
    l = __bfloat16_as_ushort(lb);
}
__device__ __forceinline__ void split2(float x, float y, uint32_t &h, uint32_t &l) {
    __nv_bfloat16 hx = __float2bfloat16(x);
    __nv_bfloat16 hy = __float2bfloat16(y);
    __nv_bfloat16 lx = __float2bfloat16(x - __bfloat162float(hx));
    __nv_bfloat16 ly = __float2bfloat16(y - __bfloat162float(hy));
    __nv_bfloat162 hp = __halves2bfloat162(hx, hy);
    __nv_bfloat162 lp = __halves2bfloat162(lx, ly);
    h = *reinterpret_cast<uint32_t*>(&hp);
    l = *reinterpret_cast<uint32_t*>(&lp);
}

// ---------------- fused fp32 -> bf16 hi/lo weight split ----------------------
// Segments (elements): Wq,Wk,Wv,Wo (1M each), Wup (4M), Wdn (4M). 16 elems/thread.
#define SEG1 (D_MODEL*D_MODEL)          // 1048576
#define CONV_CHUNKS ((4*SEG1 + 2*4*SEG1) / 16)   // 786432

__global__ __launch_bounds__(256)
void conv_all(const float* __restrict__ Wq, const float* __restrict__ Wk,
              const float* __restrict__ Wv, const float* __restrict__ Wo,
              const float* __restrict__ Wup, const float* __restrict__ Wdn,
              ushort_t* __restrict__ qh, ushort_t* __restrict__ ql,
              ushort_t* __restrict__ kh, ushort_t* __restrict__ kl,
              ushort_t* __restrict__ vh, ushort_t* __restrict__ vl,
              ushort_t* __restrict__ oh, ushort_t* __restrict__ ol,
              ushort_t* __restrict__ uh, ushort_t* __restrict__ ul,
              ushort_t* __restrict__ dh, ushort_t* __restrict__ dl)
{
    int c = blockIdx.x * 256 + threadIdx.x;
    size_t e = (size_t)c * 16;
    const float* src; ushort_t *hi, *lo; size_t off;
    if      (e < (size_t)1*SEG1) { src = Wq;  hi = qh; lo = ql; off = e; }
    else if (e < (size_t)2*SEG1) { src = Wk;  hi = kh; lo = kl; off = e - (size_t)1*SEG1; }
    else if (e < (size_t)3*SEG1) { src = Wv;  hi = vh; lo = vl; off = e - (size_t)2*SEG1; }
    else if (e < (size_t)4*SEG1) { src = Wo;  hi = oh; lo = ol; off = e - (size_t)3*SEG1; }
    else if (e < (size_t)8*SEG1) { src = Wup; hi = uh; lo = ul; off = e - (size_t)4*SEG1; }
    else                         { src = Wdn; hi = dh; lo = dl; off = e - (size_t)8*SEG1; }

    float4 v[4];
    #pragma unroll
    for (int j = 0; j < 4; j++) v[j] = *(const float4*)&src[off + j*4];
    #pragma unroll
    for (int j = 0; j < 4; j++) {
        ushort_t h[4], l[4];
        split1(v[j].x, h[0], l[0]); split1(v[j].y, h[1], l[1]);
        split1(v[j].z, h[2], l[2]); split1(v[j].w, h[3], l[3]);
        *(uint2*)&hi[off + j*4] = *(uint2*)h;
        *(uint2*)&lo[off + j*4] = *(uint2*)l;
    }
}

// ---------------- LayerNorm (writes bf16 hi/lo) ------------------------------
__global__ __launch_bounds__(256)
void ln_kernel(const float* __restrict__ x, const float* __restrict__ ms,
               const float* __restrict__ ss, ushort_t* __restrict__ yh,
               ushort_t* __restrict__ yl)
{
    int row = blockIdx.x;
    int tid = threadIdx.x;
    const float4 v = *(const float4*)&x[row*D_MODEL + tid*4];
    float s  = v.x + v.y + v.z + v.w;
    float sq = v.x*v.x + v.y*v.y + v.z*v.z + v.w*v.w;
    #pragma unroll
    for (int off = 16; off; off >>= 1) {
        s  += __shfl_xor_sync(0xffffffffu, s,  off);
        sq += __shfl_xor_sync(0xffffffffu, sq, off);
    }
    __shared__ float rs[8], rq[8];
    if ((tid & 31) == 0) { rs[tid>>5] = s; rq[tid>>5] = sq; }
    __syncthreads();
    float ts = 0.f, tq = 0.f;
    #pragma unroll
    for (int i = 0; i < 8; i++) { ts += rs[i]; tq += rq[i]; }
    float mean = ts * (1.0f/D_MODEL);
    float var  = (tq - (float)D_MODEL * mean * mean) * (1.0f/(D_MODEL-1));
    float rstd = rsqrtf(var + EPS);
    const float4 sv = *(const float4*)&ss[tid*4];
    const float4 mv = *(const float4*)&ms[tid*4];
    float o[4];
    o[0] = (v.x - mean)*rstd*sv.x + mv.x;
    o[1] = (v.y - mean)*rstd*sv.y + mv.y;
    o[2] = (v.z - mean)*rstd*sv.z + mv.z;
    o[3] = (v.w - mean)*rstd*sv.w + mv.w;
    ushort_t h[4], l[4];
    #pragma unroll
    for (int i = 0; i < 4; i++) split1(o[i], h[i], l[i]);
    *(uint2*)&yh[row*D_MODEL + tid*4] = *(uint2*)h;
    *(uint2*)&yl[row*D_MODEL + tid*4] = *(uint2*)l;
}

// ---------------- mma.sync split-bf16 GEMM (4 warps, 64x64 warp tiles) -------
// C[M,N] = (Ah+Al)[M,K] @ (Wh+Wl)[N,K]^T ; CTA tile 128x128, 2 CTAs/SM target.
// EPI: 0 -> write Ch/Cl hi/lo ; 1 -> gelu then Ch/Cl ; 2 -> Cf = acc + R (fp32)
#define ROWB  80                       // 32 bf16 = 64B + 16B pad (conflict-free)
#define ARRB  (128*ROWB)               // 10240 per array
#define STAGE (4*ARRB)                 // 40960
#define GEMM_SMEM (2*STAGE)            // 81920

template<int EPI>
__global__ __launch_bounds__(128, 2)
void gemm_mma(const ushort_t* __restrict__ Ah, const ushort_t* __restrict__ Al,
              const ushort_t* __restrict__ Wh, const ushort_t* __restrict__ Wl,
              float* __restrict__ Cf, ushort_t* __restrict__ Ch,
              ushort_t* __restrict__ Cl, const float* __restrict__ R,
              int N, int K)
{
    extern __shared__ char smem[];
    uint32_t sb = smem_u32(smem);
    uint32_t st[2] = { sb, sb + STAGE };

    int tid  = threadIdx.x;
    int lane = tid & 31;
    int wid  = tid >> 5;
    int wm   = wid & 1;        // 2 warps over M (64 rows each)
    int wn   = wid >> 1;       // 2 warps over N (64 cols each)
    int rowBase = blockIdx.y * 128;
    int colBase = blockIdx.x * 128;
    int NS = K >> 5;           // K/32 slabs

    float acc[4][8][4];
    #pragma unroll
    for (int a = 0; a < 4; a++)
        #pragma unroll
        for (int b = 0; b < 8; b++)
            #pragma unroll
            for (int c = 0; c < 4; c++) acc[a][b][c] = 0.f;

    auto load_slab = [&](uint32_t stg, int k0) {
        #pragma unroll
        for (int t = 0; t < 16; t++) {
            int c   = tid + t*128;        // 2048 16B-chunks
            int arr = c >> 9;             // 0 Ah,1 Al,2 Wh,3 Wl
            int e   = c & 511;
            int row = e >> 2;
            int c16 = (e & 3) << 4;
            const ushort_t* src = (arr == 0) ? Ah : (arr == 1) ? Al
                                 : (arr == 2) ? Wh : Wl;
            int gr = ((arr < 2) ? rowBase : colBase) + row;
            src += (size_t)gr * K + k0 + (c16 >> 1);
            uint32_t dst = stg + arr*ARRB + row*ROWB + c16;
            asm volatile("cp.async.cg.shared.global [%0], [%1], 16;" :: "r"(dst), "l"(src));
        }
        asm volatile("cp.async.commit_group;" ::: "memory");
    };

    load_slab(st[0], 0);
    load_slab(st[1], 32);

    for (int i = 0; i < NS; i++) {
        if (i + 1 < NS) asm volatile("cp.async.wait_group 1;" ::: "memory");
        else            asm volatile("cp.async.wait_group 0;" ::: "memory");
        __syncthreads();
        uint32_t stg = st[i & 1];

        #pragma unroll
        for (int ks = 0; ks < 2; ks++) {
            uint32_t ah[4][4], al[4][4];
            #pragma unroll
            for (int mi = 0; mi < 4; mi++) {
                uint32_t ra = stg + (wm*64 + mi*16 + (lane & 15))*ROWB
                            + ks*32 + (lane & 16);
                ldsm4(ah[mi][0], ah[mi][1], ah[mi][2], ah[mi][3], ra);
                ldsm4(al[mi][0], al[mi][1], al[mi][2], al[mi][3], ra + ARRB);
            }
            #pragma unroll
            for (int pr = 0; pr < 4; pr++) {
                uint32_t bh[4], bl[4];
                uint32_t rb = stg + 2*ARRB
                            + (wn*64 + pr*16 + (lane & 7) + ((lane & 16) >> 1))*ROWB
                            + ks*32 + ((lane & 8) << 1);
                ldsm4(bh[0], bh[1], bh[2], bh[3], rb);
                ldsm4(bl[0], bl[1], bl[2], bl[3], rb + ARRB);
                #pragma unroll
                for (int mi = 0; mi < 4; mi++) {
                    float* c0 = acc[mi][2*pr];
                    float* c1 = acc[mi][2*pr+1];
                    mma_bf16(c0[0],c0[1],c0[2],c0[3], ah[mi][0],ah[mi][1],ah[mi][2],ah[mi][3], bh[0],bh[1]);
                    mma_bf16(c0[0],c0[1],c0[2],c0[3], al[mi][0],al[mi][1],al[mi][2],al[mi][3], bh[0],bh[1]);
                    mma_bf16(c0[0],c0[1],c0[2],c0[3], ah[mi][0],ah[mi][1],ah[mi][2],ah[mi][3], bl[0],bl[1]);
                    mma_bf16(c1[0],c1[1],c1[2],c1[3], ah[mi][0],ah[mi][1],ah[mi][2],ah[mi][3], bh[2],bh[3]);
                    mma_bf16(c1[0],c1[1],c1[2],c1[3], al[mi][0],al[mi][1],al[mi][2],al[mi][3], bh[2],bh[3]);
                    mma_bf16(c1[0],c1[1],c1[2],c1[3], ah[mi][0],ah[mi][1],ah[mi][2],ah[mi][3], bl[2],bl[3]);
                }
            }
        }
        __syncthreads();
        if (i + 2 < NS) load_slab(stg, (i + 2)*32);
    }

    // epilogue
    int r0 = rowBase + wm*64 + (lane >> 2);
    int c0 = colBase + wn*64 + (lane & 3)*2;
    #pragma unroll
    for (int mi = 0; mi < 4; mi++) {
        #pragma unroll
        for (int n = 0; n < 8; n++) {
            float* c = acc[mi][n];
            int r  = r0 + mi*16;
            int cc = c0 + n*8;
            size_t o1 = (size_t)r * N + cc;
            size_t o2 = (size_t)(r + 8) * N + cc;
            if (EPI == 2) {
                float2 r1 = *(const float2*)&R[o1];
                float2 r2 = *(const float2*)&R[o2];
                *(float2*)&Cf[o1] = make_float2(c[0] + r1.x, c[1] + r1.y);
                *(float2*)&Cf[o2] = make_float2(c[2] + r2.x, c[3] + r2.y);
            } else {
                float v0 = c[0], v1 = c[1], v2 = c[2], v3 = c[3];
                if (EPI == 1) {
                    v0 = 0.5f*v0*(1.f + erff(v0*0.70710678118654752f));
                    v1 = 0.5f*v1*(1.f + erff(v1*0.70710678118654752f));
                    v2 = 0.5f*v2*(1.f + erff(v2*0.70710678118654752f));
                    v3 = 0.5f*v3*(1.f + erff(v3*0.70710678118654752f));
                }
                uint32_t h, l;
                split2(v0, v1, h, l);
                *(uint32_t*)&Ch[o1] = h; *(uint32_t*)&Cl[o1] = l;
                split2(v2, v3, h, l);
                *(uint32_t*)&Ch[o2] = h; *(uint32_t*)&Cl[o2] = l;
            }
        }
    }
}

// ---------------- flash attention with mma.sync (split bf16) -----------------
// CTA: 128 threads (4 warps), one (b, h, 64-query tile). Warp w: rows w*16..+15.
#define KROWB 144                       // 64 bf16 = 128B + 16B pad
#define KARR  (64*KROWB)                // 9216 per array
// layout: Qh 0, Ql 1, Kh 2, Kl 3, Vh 4, Vl 5  (x KARR)
#define ATTN_SMEM (6*KARR)

__global__ __launch_bounds__(128, 2)
void attn_mma(const ushort_t* __restrict__ Qh_, const ushort_t* __restrict__ Ql_,
              const ushort_t* __restrict__ Kh_, const ushort_t* __restrict__ Kl_,
              const ushort_t* __restrict__ Vh_, const ushort_t* __restrict__ Vl_,
              ushort_t* __restrict__ Oh, ushort_t* __restrict__ Ol)
{
    extern __shared__ char smem[];
    uint32_t sb = smem_u32(smem);
    int qt = blockIdx.x, h = blockIdx.y, b = blockIdx.z;
    int tid  = threadIdx.x;
    int lane = tid & 31;
    int w    = tid >> 5;
    int qrow0 = b*SEQ + qt*64;

    // stage Q tile (hi/lo)
    #pragma unroll
    for (int t = 0; t < 8; t++) {
        int c   = tid + t*128;           // 1024 chunks
        int arr = c >> 9;
        int e   = c & 511;
        int row = e >> 3;
        int c16 = (e & 7) << 4;
        const ushort_t* src = (arr ? Ql_ : Qh_)
            + (size_t)(qrow0 + row)*D_MODEL + h*HDIM + (c16 >> 1);
        uint4 v = *(const uint4*)src;
        *(uint4*)(smem + arr*KARR + row*KROWB + c16) = v;
    }
    __syncthreads();

    // Q fragments (held for whole kernel)
    uint32_t qh[4][4], ql[4][4];
    #pragma unroll
    for (int ks = 0; ks < 4; ks++) {
        uint32_t ra = sb + (w*16 + (lane & 15))*KROWB + ks*32 + (lane & 16);
        ldsm4(qh[ks][0], qh[ks][1], qh[ks][2], qh[ks][3], ra);
        ldsm4(ql[ks][0], ql[ks][1], ql[ks][2], ql[ks][3], ra + KARR);
    }

    float o[8][4];
    #pragma unroll
    for (int n = 0; n < 8; n++)
        #pragma unroll
        for (int j = 0; j < 4; j++) o[n][j] = 0.f;
    float m0 = -INFINITY, m1 = -INFINITY, l0 = 0.f, l1 = 0.f;

    for (int jt = 0; jt <= qt; jt++) {
        int krow0 = b*SEQ + jt*64;
        // load K,V tiles (hi/lo)
        #pragma unroll
        for (int t = 0; t < 16; t++) {
            int c   = tid + t*128;       // 2048 chunks
            int arr = c >> 9;            // 0 Kh,1 Kl,2 Vh,3 Vl
            int e   = c & 511;
            int row = e >> 3;
            int c16 = (e & 7) << 4;
            const ushort_t* src = (arr == 0) ? Kh_ : (arr == 1) ? Kl_
                                 : (arr == 2) ? Vh_ : Vl_;
            src += (size_t)(krow0 + row)*D_MODEL + h*HDIM + (c16 >> 1);
            uint4 v = *(const uint4*)src;
            *(uint4*)(smem + (2 + arr)*KARR + row*KROWB + c16) = v;
        }
        __syncthreads();

        // S = Q K^T  (n = keys)
        float s[8][4];
        #pragma unroll
        for (int n = 0; n < 8; n++)
            #pragma unroll
            for (int j = 0; j < 4; j++) s[n][j] = 0.f;

        #pragma unroll
        for (int ks = 0; ks < 4; ks++) {
            #pragma unroll
            for (int pr = 0; pr < 4; pr++) {
                uint32_t bh[4], bl[4];
                uint32_t rb = sb + 2*KARR
                            + (pr*16 + (lane & 7) + ((lane & 16) >> 1))*KROWB
                            + ks*32 + ((lane & 8) << 1);
                ldsm4(bh[0], bh[1], bh[2], bh[3], rb);
                ldsm4(bl[0], bl[1], bl[2], bl[3], rb + KARR);
                float* s0 = s[2*pr];
                float* s1 = s[2*pr+1];
                mma_bf16(s0[0],s0[1],s0[2],s0[3], qh[ks][0],qh[ks][1],qh[ks][2],qh[ks][3], bh[0],bh[1]);
                mma_bf16(s0[0],s0[1],s0[2],s0[3], ql[ks][0],ql[ks][1],ql[ks][2],ql[ks][3], bh[0],bh[1]);
                mma_bf16(s0[0],s0[1],s0[2],s0[3], qh[ks][0],qh[ks][1],qh[ks][2],qh[ks][3], bl[0],bl[1]);
                mma_bf16(s1[0],s1[1],s1[2],s1[3], qh[ks][0],qh[ks][1],qh[ks][2],qh[ks][3], bh[2],bh[3]);
                mma_bf16(s1[0],s1[1],s1[2],s1[3], ql[ks][0],ql[ks][1],ql[ks][2],ql[ks][3], bh[2],bh[3]);
                mma_bf16(s1[0],s1[1],s1[2],s1[3], qh[ks][0],qh[ks][1],qh[ks][2],qh[ks][3], bl[2],bl[3]);
            }
        }

        // scale + causal mask (diagonal tile only)
        bool diag = (jt == qt);
        int rlo = w*16 + (lane >> 2);
        int rhi = rlo + 8;
        #pragma unroll
        for (int n = 0; n < 8; n++) {
            int cA = n*8 + (lane & 3)*2;
            int cB = cA + 1;
            s[n][0] *= 0.125f; s[n][1] *= 0.125f;
            s[n][2] *= 0.125f; s[n][3] *= 0.125f;
            if (diag) {
                if (cA > rlo) s[n][0] = -INFINITY;
                if (cB > rlo) s[n][1] = -INFINITY;
                if (cA > rhi) s[n][2] = -INFINITY;
                if (cB > rhi) s[n][3] = -INFINITY;
            }
        }

        // row max across fragments + quad lanes
        float mx0 = s[0][0], mx1 = s[0][2];
        #pragma unroll
        for (int n = 0; n < 8; n++) {
            mx0 = fmaxf(mx0, fmaxf(s[n][0], s[n][1]));
            mx1 = fmaxf(mx1, fmaxf(s[n][2], s[n][3]));
        }
        mx0 = fmaxf(mx0, __shfl_xor_sync(0xffffffffu, mx0, 1));
        mx0 = fmaxf(mx0, __shfl_xor_sync(0xffffffffu, mx0, 2));
        mx1 = fmaxf(mx1, __shfl_xor_sync(0xffffffffu, mx1, 1));
        mx1 = fmaxf(mx1, __shfl_xor_sync(0xffffffffu, mx1, 2));

        float mn0 = fmaxf(m0, mx0), mn1 = fmaxf(m1, mx1);
        float al0 = __expf(m0 - mn0), al1 = __expf(m1 - mn1);

        float ls0 = 0.f, ls1 = 0.f;
        #pragma unroll
        for (int n = 0; n < 8; n++) {
            s[n][0] = __expf(s[n][0] - mn0);
            s[n][1] = __expf(s[n][1] - mn0);
            s[n][2] = __expf(s[n][2] - mn1);
            s[n][3] = __expf(s[n][3] - mn1);
            ls0 += s[n][0] + s[n][1];
            ls1 += s[n][2] + s[n][3];
        }
        ls0 += __shfl_xor_sync(0xffffffffu, ls0, 1);
        ls0 += __shfl_xor_sync(0xffffffffu, ls0, 2);
        ls1 += __shfl_xor_sync(0xffffffffu, ls1, 1);
        ls1 += __shfl_xor_sync(0xffffffffu, ls1, 2);

        l0 = l0*al0 + ls0;  l1 = l1*al1 + ls1;
        m0 = mn0;           m1 = mn1;
        #pragma unroll
        for (int n = 0; n < 8; n++) {
            o[n][0] *= al0; o[n][1] *= al0;
            o[n][2] *= al1; o[n][3] *= al1;
        }

        // PV: o += P[16x64] * V[64x64]  (k = keys, n = dims)
        #pragma unroll
        for (int kp = 0; kp < 4; kp++) {
            uint32_t ph[4], pl[4];
            split2(s[2*kp][0],   s[2*kp][1],   ph[0], pl[0]);
            split2(s[2*kp][2],   s[2*kp][3],   ph[1], pl[1]);
            split2(s[2*kp+1][0], s[2*kp+1][1], ph[2], pl[2]);
            split2(s[2*kp+1][2], s[2*kp+1][3], ph[3], pl[3]);
            #pragma unroll
            for (int pr = 0; pr < 4; pr++) {
                uint32_t vh4[4], vl4[4];
                uint32_t rv = sb + 4*KARR
                            + (kp*16 + (lane & 7) + ((lane & 8) ? 8 : 0))*KROWB
                            + pr*32 + (lane & 16);
                ldsm4t(vh4[0], vh4[1], vh4[2], vh4[3], rv);
                ldsm4t(vl4[0], vl4[1], vl4[2], vl4[3], rv + KARR);
                float* o0 = o[2*pr];
                float* o1 = o[2*pr+1];
                mma_bf16(o0[0],o0[1],o0[2],o0[3], ph[0],ph[1],ph[2],ph[3], vh4[0],vh4[1]);
                mma_bf16(o0[0],o0[1],o0[2],o0[3], pl[0],pl[1],pl[2],pl[3], vh4[0],vh4[1]);
                mma_bf16(o0[0],o0[1],o0[2],o0[3], ph[0],ph[1],ph[2],ph[3], vl4[0],vl4[1]);
                mma_bf16(o1[0],o1[1],o1[2],o1[3], ph[0],ph[1],ph[2],ph[3], vh4[2],vh4[3]);
                mma_bf16(o1[0],o1[1],o1[2],o1[3], pl[0],pl[1],pl[2],pl[3], vh4[2],vh4[3]);
                mma_bf16(o1[0],o1[1],o1[2],o1[3], ph[0],ph[1],ph[2],ph[3], vl4[2],vl4[3]);
            }
        }
        __syncthreads();   // done reading K/V before next tile overwrites
    }

    // epilogue: normalize, split to bf16 hi/lo
    float i0 = 1.f/l0, i1 = 1.f/l1;
    int r  = qrow0 + w*16 + (lane >> 2);
    int cc = h*64 + (lane & 3)*2;
    #pragma unroll
    for (int n = 0; n < 8; n++) {
        size_t o1 = (size_t)r * D_MODEL + cc + n*8;
        size_t o2 = (size_t)(r + 8) * D_MODEL + cc + n*8;
        uint32_t hh, ll;
        split2(o[n][0]*i0, o[n][1]*i0, hh, ll);
        *(uint32_t*)&Oh[o1] = hh; *(uint32_t*)&Ol[o1] = ll;
        split2(o[n][2]*i1, o[n][3]*i1, hh, ll);
        *(uint32_t*)&Oh[o2] = hh; *(uint32_t*)&Ol[o2] = ll;
    }
}

// ---------------- launcher ---------------------------------------------------
extern "C" void kernel_launch(void* const* d_in, const int* in_sizes, int n_in,
                              void* d_out, int out_size)
{
    const float* x     = (const float*)d_in[0];
    const float* Wq    = (const float*)d_in[1];
    const float* Wk    = (const float*)d_in[2];
    const float* Wv    = (const float*)d_in[3];
    const float* Wo    = (const float*)d_in[4];
    const float* Wup   = (const float*)d_in[5];
    const float* Wdown = (const float*)d_in[6];
    const float* ln1m  = (const float*)d_in[7];
    const float* ln1s  = (const float*)d_in[8];
    const float* ln2m  = (const float*)d_in[9];
    const float* ln2s  = (const float*)d_in[10];
    float* out = (float*)d_out;

    float* h1;
    ushort_t *xh, *xl, *qh, *ql, *kh, *kl, *vh, *vl, *ah, *al, *mh, *ml;
    ushort_t *wqh, *wql, *wkh, *wkl, *wvh, *wvl, *woh, *wol, *uph, *upl, *dnh, *dnl;
    cudaGetSymbolAddress((void**)&h1, g_h1);
    cudaGetSymbolAddress((void**)&xh, g_xh); cudaGetSymbolAddress((void**)&xl, g_xl);
    cudaGetSymbolAddress((void**)&qh, g_qh); cudaGetSymbolAddress((void**)&ql, g_ql);
    cudaGetSymbolAddress((void**)&kh, g_kh); cudaGetSymbolAddress((void**)&kl, g_kl);
    cudaGetSymbolAddress((void**)&vh, g_vh); cudaGetSymbolAddress((void**)&vl, g_vl);
    cudaGetSymbolAddress((void**)&ah, g_ah); cudaGetSymbolAddress((void**)&al, g_al);
    cudaGetSymbolAddress((void**)&mh, g_mh); cudaGetSymbolAddress((void**)&ml, g_ml);
    cudaGetSymbolAddress((void**)&wqh, g_wqh); cudaGetSymbolAddress((void**)&wql, g_wql);
    cudaGetSymbolAddress((void**)&wkh, g_wkh); cudaGetSymbolAddress((void**)&wkl, g_wkl);
    cudaGetSymbolAddress((void**)&wvh, g_wvh); cudaGetSymbolAddress((void**)&wvl, g_wvl);
    cudaGetSymbolAddress((void**)&woh, g_woh); cudaGetSymbolAddress((void**)&wol, g_wol);
    cudaGetSymbolAddress((void**)&uph, g_uph); cudaGetSymbolAddress((void**)&upl, g_upl);
    cudaGetSymbolAddress((void**)&dnh, g_dnh); cudaGetSymbolAddress((void**)&dnl, g_dnl);

    cudaFuncSetAttribute(gemm_mma<0>, cudaFuncAttributeMaxDynamicSharedMemorySize, GEMM_SMEM);
    cudaFuncSetAttribute(gemm_mma<1>, cudaFuncAttributeMaxDynamicSharedMemorySize, GEMM_SMEM);
    cudaFuncSetAttribute(gemm_mma<2>, cudaFuncAttributeMaxDynamicSharedMemorySize, GEMM_SMEM);
    cudaFuncSetAttribute(attn_mma,    cudaFuncAttributeMaxDynamicSharedMemorySize, ATTN_SMEM);

    // fused weight split (all 6 weights, 16 elems/thread)
    conv_all<<<CONV_CHUNKS/256, 256>>>(Wq, Wk, Wv, Wo, Wup, Wdown,
                                       wqh, wql, wkh, wkl, wvh, wvl,
                                       woh, wol, uph, upl, dnh, dnl);

    dim3 gsq(D_MODEL/128, ROWS/128);   // (8, 32)
    dim3 gup(DFF/128,     ROWS/128);   // (32, 32)

    // LN1
    ln_kernel<<<ROWS, 256>>>(x, ln1m, ln1s, xh, xl);
    // Q, K, V projections (bf16 hi/lo out)
    gemm_mma<0><<<gsq, 128, GEMM_SMEM>>>(xh, xl, wqh, wql, nullptr, qh, ql, nullptr, D_MODEL, D_MODEL);
    gemm_mma<0><<<gsq, 128, GEMM_SMEM>>>(xh, xl, wkh, wkl, nullptr, kh, kl, nullptr, D_MODEL, D_MODEL);
    gemm_mma<0><<<gsq, 128, GEMM_SMEM>>>(xh, xl, wvh, wvl, nullptr, vh, vl, nullptr, D_MODEL, D_MODEL);
    // attention
    attn_mma<<<dim3(SEQ/64, NHEADS, BATCH), 128, ATTN_SMEM>>>(qh, ql, kh, kl, vh, vl, ah, al);
    // O projection + residual
    gemm_mma<2><<<gsq, 128, GEMM_SMEM>>>(ah, al, woh, wol, h1, nullptr, nullptr, x, D_MODEL, D_MODEL);
    // LN2
    ln_kernel<<<ROWS, 256>>>(h1, ln2m, ln2s, xh, xl);
    // up-proj + GELU
    gemm_mma<1><<<gup, 128, GEMM_SMEM>>>(xh, xl, uph, upl, nullptr, mh, ml, nullptr, DFF, D_MODEL);
    // down-proj + residual -> output
    gemm_mma<2><<<gsq, 128, GEMM_SMEM>>>(mh, ml, dnh, dnl, out, nullptr, nullptr, h1, D_MODEL, DFF);
}